// round 3
// baseline (speedup 1.0000x reference)
#include <cuda_runtime.h>
#include <math.h>

// x: [32, 16, 512, 512] fp32. Stats over spatial dims per (b, c).
// out: [32, 64] = concat(mean[16], std[16], max[16], min[16]) per batch row.
//
// Two-phase: 4096 partial CTAs (8 segments/channel, 128 KB each) to kill
// wave quantization (512 CTAs = 3.46 waves -> 15% tail; 4096 = 27.7 -> 1.2%),
// then a tiny deterministic combine kernel.

static constexpr int HW      = 512 * 512;     // 262144 elems / channel
static constexpr int NCHAN   = 32 * 16;       // 512 channels
static constexpr int NSEG    = 8;             // segments per channel
static constexpr int SEG_EL  = HW / NSEG;     // 32768 elems / segment
static constexpr int SEG_V4  = SEG_EL / 4;    // 8192 float4 / segment
static constexpr int NTHR    = 256;

// Partial per (channel, segment): {sum, sumsq, max, min}
__device__ float4 g_partials[NCHAN * NSEG];

__global__ __launch_bounds__(NTHR, 1)
void stats_partial_kernel(const float* __restrict__ x) {
    const int gid  = blockIdx.x;          // 0 .. 4095
    const int ch   = gid >> 3;            // channel
    const int seg  = gid & 7;             // segment within channel

    const float4* __restrict__ p = reinterpret_cast<const float4*>(
        x + (size_t)ch * HW + (size_t)seg * SEG_EL);

    float sum   = 0.0f;
    float sumsq = 0.0f;
    float mx    = -INFINITY;
    float mn    =  INFINITY;

    #pragma unroll 4
    for (int i = threadIdx.x; i < SEG_V4; i += NTHR) {
        float4 v = p[i];
        sum   += (v.x + v.y) + (v.z + v.w);
        sumsq  = fmaf(v.x, v.x, sumsq);
        sumsq  = fmaf(v.y, v.y, sumsq);
        sumsq  = fmaf(v.z, v.z, sumsq);
        sumsq  = fmaf(v.w, v.w, sumsq);
        mx = fmaxf(mx, fmaxf(fmaxf(v.x, v.y), fmaxf(v.z, v.w)));
        mn = fminf(mn, fminf(fminf(v.x, v.y), fminf(v.z, v.w)));
    }

    // Warp reduction
    #pragma unroll
    for (int o = 16; o > 0; o >>= 1) {
        sum   += __shfl_xor_sync(0xffffffffu, sum,   o);
        sumsq += __shfl_xor_sync(0xffffffffu, sumsq, o);
        mx = fmaxf(mx, __shfl_xor_sync(0xffffffffu, mx, o));
        mn = fminf(mn, __shfl_xor_sync(0xffffffffu, mn, o));
    }

    __shared__ float s_sum[8], s_sq[8], s_mx[8], s_mn[8];
    const int wid = threadIdx.x >> 5;
    const int lid = threadIdx.x & 31;
    if (lid == 0) {
        s_sum[wid] = sum;
        s_sq[wid]  = sumsq;
        s_mx[wid]  = mx;
        s_mn[wid]  = mn;
    }
    __syncthreads();

    if (threadIdx.x == 0) {
        float ts = 0.0f, tq = 0.0f, tmx = -INFINITY, tmn = INFINITY;
        #pragma unroll
        for (int w = 0; w < 8; w++) {
            ts += s_sum[w];
            tq += s_sq[w];
            tmx = fmaxf(tmx, s_mx[w]);
            tmn = fminf(tmn, s_mn[w]);
        }
        g_partials[gid] = make_float4(ts, tq, tmx, tmn);
    }
}

// One thread per channel; fixed combine order -> deterministic.
__global__ __launch_bounds__(NTHR, 1)
void stats_combine_kernel(float* __restrict__ out) {
    const int ch = blockIdx.x * NTHR + threadIdx.x;
    if (ch >= NCHAN) return;
    const int b = ch >> 4;
    const int c = ch & 15;

    float ts = 0.0f, tq = 0.0f, tmx = -INFINITY, tmn = INFINITY;
    #pragma unroll
    for (int s = 0; s < NSEG; s++) {
        float4 pv = g_partials[ch * NSEG + s];
        ts += pv.x;
        tq += pv.y;
        tmx = fmaxf(tmx, pv.z);
        tmn = fminf(tmn, pv.w);
    }

    const float mean = ts / (float)HW;
    const float var  = (tq - ts * mean) / (float)(HW - 1);
    const float sd   = sqrtf(fmaxf(var, 0.0f));

    float* __restrict__ ob = out + (size_t)b * 64;
    ob[c]      = mean;
    ob[16 + c] = sd;
    ob[32 + c] = tmx;
    ob[48 + c] = tmn;
}

extern "C" void kernel_launch(void* const* d_in, const int* in_sizes, int n_in,
                              void* d_out, int out_size) {
    const float* x = (const float*)d_in[0];
    float* out = (float*)d_out;
    stats_partial_kernel<<<NCHAN * NSEG, NTHR>>>(x);
    stats_combine_kernel<<<(NCHAN + NTHR - 1) / NTHR, NTHR>>>(out);
}